// round 7
// baseline (speedup 1.0000x reference)
#include <cuda_runtime.h>
#include <math.h>

#define BB 4
#define SS 2048
#define DD 512
#define HH 8
#define HD 64
#define BH (BB*HH)

__device__ float    g_q[BH * SS * HD];
__device__ float    g_k[BH * SS * HD];
__device__ float    g_v[BH * SS * HD];
__device__ float    g_x[BB * SS * DD];
__device__ unsigned g_mbits[BB * SS * (SS/32)];

// ---------------------------------------------------------------------------
__device__ __forceinline__ unsigned f2tf(float x) {
    unsigned r;
    asm("cvt.rna.tf32.f32 %0, %1;" : "=r"(r) : "f"(x));
    return r;
}
__device__ __forceinline__ void mma_tf32(float c[4], const unsigned a[4], const unsigned b[2]) {
    asm volatile(
        "mma.sync.aligned.m16n8k8.row.col.f32.tf32.tf32.f32 "
        "{%0,%1,%2,%3},{%4,%5,%6,%7},{%8,%9},{%0,%1,%2,%3};"
        : "+f"(c[0]), "+f"(c[1]), "+f"(c[2]), "+f"(c[3])
        : "r"(a[0]), "r"(a[1]), "r"(a[2]), "r"(a[3]), "r"(b[0]), "r"(b[1]));
}
__device__ __forceinline__ void cp16(void* dst_smem, const void* src_gmem) {
    unsigned d = (unsigned)__cvta_generic_to_shared(dst_smem);
    asm volatile("cp.async.cg.shared.global [%0], [%1], 16;" :: "r"(d), "l"(src_gmem));
}
#define CP_COMMIT()  asm volatile("cp.async.commit_group;")
#define CP_WAIT0()   asm volatile("cp.async.wait_group 0;")
#define CP_WAIT1()   asm volatile("cp.async.wait_group 1;")

__device__ __forceinline__ void cvt_inplace(unsigned* p) {
    float4 v = *(float4*)p;
    *(uint4*)p = make_uint4(f2tf(v.x), f2tf(v.y), f2tf(v.z), f2tf(v.w));
}

// ---------------------------------------------------------------------------
__global__ __launch_bounds__(256) void pack_mask_kernel(
    const int* __restrict__ mask, unsigned* __restrict__ bits)
{
    int w = blockIdx.x * 256 + threadIdx.x;
    const int4* p = (const int4*)(mask + (size_t)w * 32);
    unsigned v = 0;
    #pragma unroll
    for (int i = 0; i < 8; i++) {
        int4 q = p[i];
        v |= (unsigned)(q.x != 0) << (i * 4 + 0);
        v |= (unsigned)(q.y != 0) << (i * 4 + 1);
        v |= (unsigned)(q.z != 0) << (i * 4 + 2);
        v |= (unsigned)(q.w != 0) << (i * 4 + 3);
    }
    bits[w] = v;
}

// ---------------------------------------------------------------------------
// Projection GEMM: C = X @ W^T + bias. Block 128x128, 256 thr (8 warps 2mx4n,
// warp 64x32). cp.async raw fp32 double-buffer + in-place tf32 convert.
// ---------------------------------------------------------------------------
__device__ __forceinline__ void proj_issue(
    unsigned* Ab, unsigned* Bb, const float* X, const float* W,
    int m0, int n0, int kb, int t)
{
    #pragma unroll
    for (int i = 0; i < 4; i++) {
        int id = i * 256 + t;
        int r = id >> 3, c4 = (id & 7) * 4;
        cp16(Ab + r * 36 + c4, X + (size_t)(m0 + r) * DD + kb + c4);
        cp16(Bb + r * 36 + c4, W + (size_t)(n0 + r) * DD + kb + c4);
    }
    CP_COMMIT();
}

__global__ __launch_bounds__(256) void proj_mma(
    const float* __restrict__ X, const float* __restrict__ W,
    const float* __restrict__ bias, float* __restrict__ out, int scatter)
{
    extern __shared__ unsigned psm[];
    unsigned* Ab[2] = { psm,          psm + 4608 };   // [128][36]
    unsigned* Bb[2] = { psm + 9216,   psm + 13824 };

    const int t = threadIdx.x;
    const int warp = t >> 5, lane = t & 31;
    const int wm = warp >> 2, wn = warp & 3;
    const int g = lane >> 2, tig = lane & 3;
    const int m0 = blockIdx.y * 128, n0 = blockIdx.x * 128;

    float acc[4][4][4] = {};

    proj_issue(Ab[0], Bb[0], X, W, m0, n0, 0, t);

    for (int kt = 0; kt < 16; kt++) {
        __syncthreads();
        if (kt < 15) { proj_issue(Ab[(kt+1)&1], Bb[(kt+1)&1], X, W, m0, n0, (kt+1)*32, t); CP_WAIT1(); }
        else CP_WAIT0();
        __syncthreads();
        unsigned* Ac = Ab[kt & 1];
        unsigned* Bc = Bb[kt & 1];
        #pragma unroll
        for (int i = 0; i < 4; i++) {
            int id = i * 256 + t;
            int r = id >> 3, c4 = (id & 7) * 4;
            cvt_inplace(Ac + r * 36 + c4);
            cvt_inplace(Bc + r * 36 + c4);
        }
        __syncthreads();

        #pragma unroll
        for (int kk = 0; kk < 32; kk += 8) {
            unsigned af[4][4], bf[4][2];
            #pragma unroll
            for (int mt = 0; mt < 4; mt++) {
                int mrow = wm * 64 + mt * 16;
                af[mt][0] = Ac[(mrow + g) * 36 + kk + tig];
                af[mt][1] = Ac[(mrow + g + 8) * 36 + kk + tig];
                af[mt][2] = Ac[(mrow + g) * 36 + kk + tig + 4];
                af[mt][3] = Ac[(mrow + g + 8) * 36 + kk + tig + 4];
            }
            #pragma unroll
            for (int nt = 0; nt < 4; nt++) {
                int ncol = wn * 32 + nt * 8 + g;
                bf[nt][0] = Bc[ncol * 36 + kk + tig];
                bf[nt][1] = Bc[ncol * 36 + kk + tig + 4];
            }
            #pragma unroll
            for (int mt = 0; mt < 4; mt++)
                #pragma unroll
                for (int nt = 0; nt < 4; nt++)
                    mma_tf32(acc[mt][nt], af[mt], bf[nt]);
        }
    }

    #pragma unroll
    for (int nt = 0; nt < 4; nt++) {
        const int col = n0 + wn * 32 + nt * 8 + 2 * tig;
        const float b0v = bias[col], b1v = bias[col + 1];
        #pragma unroll
        for (int mt = 0; mt < 4; mt++) {
            #pragma unroll
            for (int half = 0; half < 2; half++) {
                int m = m0 + wm * 64 + mt * 16 + g + half * 8;
                float2 v;
                v.x = acc[mt][nt][half * 2 + 0] + b0v;
                v.y = acc[mt][nt][half * 2 + 1] + b1v;
                if (scatter) {
                    int b = m >> 11, s = m & (SS - 1);
                    int h = col >> 6, hd = col & (HD - 1);
                    *(float2*)&out[(((size_t)(b * HH + h)) * SS + s) * HD + hd] = v;
                } else {
                    *(float2*)&out[(size_t)m * DD + col] = v;
                }
            }
        }
    }
}

// ---------------------------------------------------------------------------
// Fused attention: 512 threads, 16 warps (4m x 4n). Block owns 128 q-rows.
// ---------------------------------------------------------------------------
#define QS_OFF   0
#define KB_OFF   8704
#define VS_OFF   26112
#define PS_OFF   35328
#define RS_OFF   52224
#define ATTN_SMEM_W 52352

// FULL tile copy: 128 rows x 64 floats = 2048 float4s (4 per thread @512thr)
__device__ __forceinline__ void attn_issue(unsigned* buf, const float* src, int n0, int stride, int t)
{
    #pragma unroll
    for (int i = 0; i < 4; i++) {
        int id = i * 512 + t;
        int r = id >> 4, c4 = (id & 15) * 4;
        cp16(buf + r * stride + c4, src + (size_t)(n0 + r) * HD + c4);
    }
    CP_COMMIT();
}

__device__ __forceinline__ void attn_convert(unsigned* buf, int stride, int t)
{
    #pragma unroll
    for (int i = 0; i < 4; i++) {
        int f = i * 512 + t;
        int r = f >> 4, c4 = (f & 15) * 4;
        cvt_inplace(buf + r * stride + c4);
    }
}

__global__ __launch_bounds__(512) void attn_fused(float* __restrict__ dist)
{
    extern __shared__ unsigned sm[];
    unsigned* Qs = sm + QS_OFF;
    unsigned* Kb[2] = { sm + KB_OFF, sm + KB_OFF + 8704 };
    unsigned* Vs = sm + VS_OFF;
    unsigned* Ps = sm + PS_OFF;
    float* rowsum = (float*)(sm + RS_OFF);

    const int t = threadIdx.x;
    const int warp = t >> 5, lane = t & 31;
    const int wm = warp >> 2, wn = warp & 3;   // 4m x 4n
    const int g = lane >> 2, tig = lane & 3;
    const int bh = blockIdx.y, b = bh >> 3, h = bh & 7;
    const int m0 = blockIdx.x * 128;

    const float* q = g_q + (size_t)bh * SS * HD;
    const float* k = g_k + (size_t)bh * SS * HD;
    const float* v = g_v + (size_t)bh * SS * HD;

    // prologue: K(0) + Q in flight, then convert Q
    attn_issue(Kb[0], k, 0, 68, t);
    attn_issue(Qs, q, m0, 68, t);
    CP_WAIT0();
    __syncthreads();
    attn_convert(Qs, 68, t);
    if (t < 128) rowsum[t] = 0.0f;

    float rs[2][2] = {};

    // ======== Phase A: row sums ========
    for (int it = 0; it < 16; it++) {
        __syncthreads();
        attn_issue(Kb[(it + 1) & 1], k, ((it + 1) & 15) * 128, 68, t);
        CP_WAIT1();
        __syncthreads();
        unsigned* Kc = Kb[it & 1];
        attn_convert(Kc, 68, t);
        __syncthreads();
        const int n0 = it * 128;

        float acc[2][4][4] = {};
        #pragma unroll
        for (int kk = 0; kk < 64; kk += 8) {
            unsigned af[2][4], bf[4][2];
            #pragma unroll
            for (int mt = 0; mt < 2; mt++) {
                int mrow = wm * 32 + mt * 16;
                af[mt][0] = Qs[(mrow + g) * 68 + kk + tig];
                af[mt][1] = Qs[(mrow + g + 8) * 68 + kk + tig];
                af[mt][2] = Qs[(mrow + g) * 68 + kk + tig + 4];
                af[mt][3] = Qs[(mrow + g + 8) * 68 + kk + tig + 4];
            }
            #pragma unroll
            for (int nt = 0; nt < 4; nt++) {
                int ncol = wn * 32 + nt * 8 + g;
                bf[nt][0] = Kc[ncol * 68 + kk + tig];
                bf[nt][1] = Kc[ncol * 68 + kk + tig + 4];
            }
            #pragma unroll
            for (int mt = 0; mt < 2; mt++)
                #pragma unroll
                for (int nt = 0; nt < 4; nt++)
                    mma_tf32(acc[mt][nt], af[mt], bf[nt]);
        }

        #pragma unroll
        for (int mt = 0; mt < 2; mt++) {
            #pragma unroll
            for (int half = 0; half < 2; half++) {
                int row = m0 + wm * 32 + mt * 16 + g + half * 8;
                unsigned mb = g_mbits[((size_t)b * SS + row) * (SS/32) + (n0 >> 5) + wn];
                #pragma unroll
                for (int nt = 0; nt < 4; nt++) {
                    int nloc = nt * 8 + 2 * tig;
                    float e0 = ((mb >> nloc) & 1u) ? 0.0f : __expf(acc[mt][nt][half*2+0] * 0.125f);
                    float e1 = ((mb >> (nloc+1)) & 1u) ? 0.0f : __expf(acc[mt][nt][half*2+1] * 0.125f);
                    rs[mt][half] += e0 + e1;
                }
            }
        }
    }

    // reduce row sums
    #pragma unroll
    for (int mt = 0; mt < 2; mt++)
        #pragma unroll
        for (int half = 0; half < 2; half++) {
            float s = rs[mt][half];
            s += __shfl_xor_sync(0xffffffffu, s, 1);
            s += __shfl_xor_sync(0xffffffffu, s, 2);
            if (tig == 0)
                atomicAdd(&rowsum[wm * 32 + mt * 16 + g + half * 8], s);
        }
    attn_issue(Vs, v, 0, 72, t);
    __syncthreads();
    if (t < 128) rowsum[t] = 1.0f / rowsum[t];

    // ======== Phase B: recompute, normalize, write dist once, PV ========
    float y[2][2][4] = {};
    const size_t dbase = (size_t)bh * SS * SS;

    for (int it = 0; it < 16; it++) {
        const int n0 = it * 128;
        CP_WAIT1();              // K(it) arrived (V(it) may be pending)
        __syncthreads();         // publishes rowsum on it==0
        unsigned* Kc = Kb[it & 1];
        attn_convert(Kc, 68, t);
        __syncthreads();

        float acc[2][4][4] = {};
        #pragma unroll
        for (int kk = 0; kk < 64; kk += 8) {
            unsigned af[2][4], bf[4][2];
            #pragma unroll
            for (int mt = 0; mt < 2; mt++) {
                int mrow = wm * 32 + mt * 16;
                af[mt][0] = Qs[(mrow + g) * 68 + kk + tig];
                af[mt][1] = Qs[(mrow + g + 8) * 68 + kk + tig];
                af[mt][2] = Qs[(mrow + g) * 68 + kk + tig + 4];
                af[mt][3] = Qs[(mrow + g + 8) * 68 + kk + tig + 4];
            }
            #pragma unroll
            for (int nt = 0; nt < 4; nt++) {
                int ncol = wn * 32 + nt * 8 + g;
                bf[nt][0] = Kc[ncol * 68 + kk + tig];
                bf[nt][1] = Kc[ncol * 68 + kk + tig + 4];
            }
            #pragma unroll
            for (int mt = 0; mt < 2; mt++)
                #pragma unroll
                for (int nt = 0; nt < 4; nt++)
                    mma_tf32(acc[mt][nt], af[mt], bf[nt]);
        }

        attn_issue(Kb[(it + 1) & 1], k, ((it + 1) & 15) * 128, 68, t);

        // epilogue: normalize, write dist, deposit tf32 P
        #pragma unroll
        for (int mt = 0; mt < 2; mt++) {
            #pragma unroll
            for (int half = 0; half < 2; half++) {
                int rowl = wm * 32 + mt * 16 + g + half * 8;
                int row = m0 + rowl;
                unsigned mb = g_mbits[((size_t)b * SS + row) * (SS/32) + (n0 >> 5) + wn];
                float inv = rowsum[rowl];
                #pragma unroll
                for (int nt = 0; nt < 4; nt++) {
                    int nloc = nt * 8 + 2 * tig;
                    float e0 = ((mb >> nloc) & 1u) ? 0.0f : __expf(acc[mt][nt][half*2+0] * 0.125f) * inv;
                    float e1 = ((mb >> (nloc+1)) & 1u) ? 0.0f : __expf(acc[mt][nt][half*2+1] * 0.125f) * inv;
                    float2 ev; ev.x = e0; ev.y = e1;
                    *(float2*)&dist[dbase + (size_t)row * SS + n0 + wn * 32 + nloc] = ev;
                    uint2 pv; pv.x = f2tf(e0); pv.y = f2tf(e1);
                    *(uint2*)&Ps[rowl * 132 + wn * 32 + nloc] = pv;
                }
            }
        }

        CP_WAIT1();              // V(it) arrived (K(it+1) pending)
        __syncthreads();         // Ps + raw V visible
        attn_convert(Vs, 72, t);
        __syncthreads();

        // PV: y += P[128x128] @ V[128x64]; warp tile 32x16
        #pragma unroll
        for (int kk = 0; kk < 128; kk += 8) {
            unsigned af[2][4], bf[2][2];
            #pragma unroll
            for (int mt = 0; mt < 2; mt++) {
                int mrow = wm * 32 + mt * 16;
                af[mt][0] = Ps[(mrow + g) * 132 + kk + tig];
                af[mt][1] = Ps[(mrow + g + 8) * 132 + kk + tig];
                af[mt][2] = Ps[(mrow + g) * 132 + kk + tig + 4];
                af[mt][3] = Ps[(mrow + g + 8) * 132 + kk + tig + 4];
            }
            #pragma unroll
            for (int nt = 0; nt < 2; nt++) {
                int ncol = wn * 16 + nt * 8 + g;
                bf[nt][0] = Vs[(kk + tig) * 72 + ncol];
                bf[nt][1] = Vs[(kk + tig + 4) * 72 + ncol];
            }
            #pragma unroll
            for (int mt = 0; mt < 2; mt++)
                #pragma unroll
                for (int nt = 0; nt < 2; nt++)
                    mma_tf32(y[mt][nt], af[mt], bf[nt]);
        }
        __syncthreads();         // P/V consumed
        attn_issue(Vs, v, ((it + 1) & 15) * 128, 72, t);
    }
    CP_WAIT0();

    // output
    #pragma unroll
    for (int mt = 0; mt < 2; mt++) {
        #pragma unroll
        for (int nt = 0; nt < 2; nt++) {
            #pragma unroll
            for (int half = 0; half < 2; half++) {
                int row = m0 + wm * 32 + mt * 16 + g + half * 8;
                int col = wn * 16 + nt * 8 + 2 * tig;
                float2 o;
                o.x = y[mt][nt][half * 2 + 0];
                o.y = y[mt][nt][half * 2 + 1];
                *(float2*)&g_x[((size_t)(b * SS + row)) * DD + h * HD + col] = o;
            }
        }
    }
}

// ---------------------------------------------------------------------------
extern "C" void kernel_launch(void* const* d_in, const int* in_sizes, int n_in,
                              void* d_out, int out_size)
{
    const float* Q  = (const float*)d_in[0];
    const float* K  = (const float*)d_in[1];
    const float* V  = (const float*)d_in[2];
    const int*   mask = (const int*)d_in[3];
    const float* Wq = (const float*)d_in[4];
    const float* bq = (const float*)d_in[5];
    const float* Wk = (const float*)d_in[6];
    const float* bk = (const float*)d_in[7];
    const float* Wv = (const float*)d_in[8];
    const float* bv = (const float*)d_in[9];
    const float* Wo = (const float*)d_in[10];
    const float* bo = (const float*)d_in[11];

    float* out_x    = (float*)d_out;
    float* out_dist = (float*)d_out + (size_t)BB * SS * DD;

    void* pq; void* pk; void* pv; void* px; void* pbits;
    cudaGetSymbolAddress(&pq, g_q);
    cudaGetSymbolAddress(&pk, g_k);
    cudaGetSymbolAddress(&pv, g_v);
    cudaGetSymbolAddress(&px, g_x);
    cudaGetSymbolAddress(&pbits, g_mbits);

    const int PROJ_SMEM = 18432 * 4;           // 73,728 B
    const int ATTN_SMEM = ATTN_SMEM_W * 4;     // 209,408 B
    cudaFuncSetAttribute(proj_mma, cudaFuncAttributeMaxDynamicSharedMemorySize, PROJ_SMEM);
    cudaFuncSetAttribute(attn_fused, cudaFuncAttributeMaxDynamicSharedMemorySize, ATTN_SMEM);

    pack_mask_kernel<<<(BB * SS * (SS/32)) / 256, 256>>>(mask, (unsigned*)pbits);

    dim3 gproj(DD / 128, (BB * SS) / 128);                  // (4, 64) = 256 blocks
    proj_mma<<<gproj, 256, PROJ_SMEM>>>(Q, Wq, bq, (float*)pq, 1);
    proj_mma<<<gproj, 256, PROJ_SMEM>>>(K, Wk, bk, (float*)pk, 1);
    proj_mma<<<gproj, 256, PROJ_SMEM>>>(V, Wv, bv, (float*)pv, 1);

    dim3 gattn(SS / 128, BH);                               // (16, 32)
    attn_fused<<<gattn, 512, ATTN_SMEM>>>(out_dist);

    proj_mma<<<gproj, 256, PROJ_SMEM>>>((const float*)px, Wo, bo, out_x, 0);
}